// round 11
// baseline (speedup 1.0000x reference)
#include <cuda_runtime.h>

#define HH    512
#define WW    512
#define HW    (HH * WW)
#define PAD   8
#define NKH   32
#define NKW   32
#define NK    1024
#define NC    33            // stride cells per dim (528/16)
#define BATCH 64
#define RPAD  36            // lane-row stride (words): conflict-free LDS.128

// Init: out[b,n] = bias[n], vectorized. Full overwrite -> replay idempotent.
__global__ __launch_bounds__(256) void bslc_init(
    const float4* __restrict__ bias4, float4* __restrict__ out4)
{
    const int idx = blockIdx.x * 256 + threadIdx.x;   // 16384 float4 slots
    out4[idx] = bias4[idx & 255];
}

// Block = (16x16 stride cell, batch-half of 32). Cell (Ri,Ci) covers padded
// pixels [16Ri,16Ri+16)x[16Ci,16Ci+16); these feed windows (Ri-i, Ci-j),
// i,j in {0,1}, at kernel offsets (dy+16i, dx+16j) -> quadrants q=i*2+j.
//
// Warp = (row-half h = w&1, batch-octet bg = w>>1). Lane owns ONE pixel-quad
// (16 weight regs). The octet is processed in TWO passes of 4 batches:
// xv[4] preload (MLP=4) keeps regs ~48 so 5 blocks/SM stay resident
// (40 warps, 62.5% occ) -- occupancy does the latency hiding instead of
// per-warp MLP. sred is sized for one pass (18.4KB). Phase 2 per pass:
// 64 threads sum conflict-free LDS.128 rows and atomicAdd into
// bias-initialized out (4 atomics per (b,n) total).
__global__ __launch_bounds__(256, 5) void bslc_main(
    const float* __restrict__ x,       // (64,1,512,512)
    const float* __restrict__ weight,  // (NK,1024)
    float* __restrict__ out)           // (64,NK) = bias-initialized
{
    // [q][h][bg][t][lane + pad], one 4-batch pass at a time
    __shared__ __align__(16) float sred[4][2][4][4][RPAD];

    const int cell = blockIdx.x;
    const int B0   = blockIdx.y * 32;      // batch-half base
    const int Ri = cell / NC, Ci = cell % NC;
    const int tid  = threadIdx.x;
    const int lane = tid & 31;
    const int warp = tid >> 5;
    const int h    = warp & 1;             // cell row-half
    const int bg   = warp >> 1;            // batch-octet (0..3)

    // Lane's pixel-quad within its half-cell
    const int dy  = h * 8 + (lane >> 2);
    const int dx4 = (lane & 3) << 2;
    const int uy  = Ri * 16 + dy  - PAD;
    const int ux  = Ci * 16 + dx4 - PAD;
    const bool ok = ((unsigned)uy < (unsigned)HH) &&
                    ((unsigned)ux <= (unsigned)(WW - 4));
    const int off = uy * WW + ux;

    // Quadrant windows + weights (4 float4/lane; full 4-sided check)
    float4 wq[4];
#pragma unroll
    for (int q = 0; q < 4; q++) {
        const int r = Ri - (q >> 1), c = Ci - (q & 1);
        const bool v = (r >= 0) && (r < NKH) && (c >= 0) && (c < NKW);
        float4 w = make_float4(0.f, 0.f, 0.f, 0.f);
        if (v)
            w = *reinterpret_cast<const float4*>(
                    weight + (r * NKW + c) * 1024
                           + (dy  + 16 * (q >> 1)) * 32
                           + (dx4 + 16 * (q & 1)));
        wq[q] = w;
    }

    const float* __restrict__ xw = x + (size_t)(B0 + bg * 8) * HW + off;

#pragma unroll
    for (int p = 0; p < 2; p++) {
        // Preload 4 batches: 4 independent LDG.128 per warp
        float4 xv[4];
#pragma unroll
        for (int t = 0; t < 4; t++) {
            xv[t] = make_float4(0.f, 0.f, 0.f, 0.f);
            if (ok)
                xv[t] = *reinterpret_cast<const float4*>(
                            xw + (size_t)(p * 4 + t) * HW);
        }

        // 16 FMAs + 4 STS per batch
#pragma unroll
        for (int t = 0; t < 4; t++) {
#pragma unroll
            for (int q = 0; q < 4; q++) {
                const float s =
                    fmaf(xv[t].x, wq[q].x,
                    fmaf(xv[t].y, wq[q].y,
                    fmaf(xv[t].z, wq[q].z, xv[t].w * wq[q].w)));
                sred[q][h][bg][t][lane] = s;   // stride-1, conflict-free
            }
        }

        __syncthreads();

        // Phase 2: 64 threads -> (q = tid>>4, lb = bg*4 + t = tid&15)
        if (tid < 64) {
            const int q  = tid >> 4;
            const int lb = tid & 15;
            const float* r0 = &sred[q][0][lb >> 2][lb & 3][0];
            const float* r1 = &sred[q][1][lb >> 2][lb & 3][0];
            float4 s4 = make_float4(0.f, 0.f, 0.f, 0.f);
#pragma unroll
            for (int i = 0; i < 8; i++) {
                const float4 a  = reinterpret_cast<const float4*>(r0)[i];
                const float4 b4 = reinterpret_cast<const float4*>(r1)[i];
                s4.x += a.x + b4.x; s4.y += a.y + b4.y;
                s4.z += a.z + b4.z; s4.w += a.w + b4.w;
            }
            const float s = (s4.x + s4.y) + (s4.z + s4.w);

            const int b = B0 + (lb >> 2) * 8 + p * 4 + (lb & 3);
            const int r = Ri - (q >> 1), c = Ci - (q & 1);
            if (r >= 0 && r < NKH && c >= 0 && c < NKW)
                atomicAdd(out + (size_t)b * NK + r * NKW + c, s);
        }
        if (p == 0) __syncthreads();           // sred reused by next pass
    }
}

extern "C" void kernel_launch(void* const* d_in, const int* in_sizes, int n_in,
                              void* d_out, int out_size)
{
    const float* x      = (const float*)d_in[0];   // (64,1,512,512) fp32
    const float* weight = (const float*)d_in[1];   // (1024,1024)    fp32
    const float* bias   = (const float*)d_in[2];   // (1024,)        fp32
    float*       out    = (float*)d_out;           // (64,32,32)     fp32

    bslc_init<<<(BATCH * NK) / (256 * 4), 256>>>(
        (const float4*)bias, (float4*)out);

    dim3 grid(NC * NC, 2);                         // cell x batch-half
    bslc_main<<<grid, 256>>>(x, weight, out);
}